// round 14
// baseline (speedup 1.0000x reference)
#include <cuda_runtime.h>
#include <cuda_bf16.h>

#define MAX_PART 65536
#define SEG_F4   1000          // float4 per segment = 16 KB

__device__ float g_part[MAX_PART];

__device__ __forceinline__ float ex2(float x) {
    float y;
    asm("ex2.approx.f32 %0, %1;" : "=f"(y) : "f"(x));
    return y;
}

// Segment sweep: one 16KB CONTIGUOUS segment per block. The ~1184 resident
// blocks cover a dense ~19MB window sweeping through the matrix (vs ~148MB
// scattered footprint of the row-per-block designs, which all capped at
// ~5 TB/s regardless of warp-level MLP — R3..R12 post-mortem).
__global__ void __launch_bounds__(256) cosarc_sweep_kernel(
    const float* __restrict__ preds,
    int n4, int nspr)               // n4 = V/4, nspr = segments per row
{
    const int b   = blockIdx.x;
    const int row = b / nspr;
    const int seg = b - row * nspr;
    const int base = seg * SEG_F4;

    const float4* p4 = reinterpret_cast<const float4*>(preds) + (size_t)row * n4 + base;
    const int lim = min(SEG_F4, n4 - base);   // 1000 except a short last segment

    const int tid = threadIdx.x;
    const float C = 30.0f * 1.4426950408889634f;   // exp(30x) = exp2(C*x)
    float s0 = 0.f, s1 = 0.f, s2 = 0.f, s3 = 0.f;

    // 4 front-batched independent LDG.128 (covers 1024 >= SEG_F4).
    const int i0 = tid, i1 = tid + 256, i2 = tid + 512, i3 = tid + 768;
    float4 a, bb, c, d;
    bool v0 = i0 < lim, v1 = i1 < lim, v2 = i2 < lim, v3 = i3 < lim;
    if (v0) a  = __ldg(p4 + i0);
    if (v1) bb = __ldg(p4 + i1);
    if (v2) c  = __ldg(p4 + i2);
    if (v3) d  = __ldg(p4 + i3);
    if (v0) { s0 += ex2(a.x  * C) + ex2(a.y  * C); s1 += ex2(a.z  * C) + ex2(a.w  * C); }
    if (v1) { s2 += ex2(bb.x * C) + ex2(bb.y * C); s3 += ex2(bb.z * C) + ex2(bb.w * C); }
    if (v2) { s0 += ex2(c.x  * C) + ex2(c.y  * C); s1 += ex2(c.z  * C) + ex2(c.w  * C); }
    if (v3) { s2 += ex2(d.x  * C) + ex2(d.y  * C); s3 += ex2(d.z  * C) + ex2(d.w  * C); }

    float sum = (s0 + s1) + (s2 + s3);
    #pragma unroll
    for (int o = 16; o > 0; o >>= 1)
        sum += __shfl_xor_sync(0xffffffffu, sum, o);

    __shared__ float warpsum[8];
    const int wid = tid >> 5, lid = tid & 31;
    if (lid == 0) warpsum[wid] = sum;
    __syncthreads();

    if (tid == 0) {
        float tot = 0.f;
        #pragma unroll
        for (int w = 0; w < 8; w++) tot += warpsum[w];
        g_part[b] = tot;
    }
}

// Finalize: combine segment partials per row, epilogue, deterministic mean.
__global__ void __launch_bounds__(256) cosarc_final_kernel(
    const float* __restrict__ preds,
    const int* __restrict__ labels,     // int32 (JAX x64 disabled)
    float* __restrict__ out,
    int V, int B, int nspr)
{
    const int tid = threadIdx.x;
    const float C = 30.0f * 1.4426950408889634f;

    double acc = 0.0;
    for (int r = tid; r < B; r += 256) {
        float tot = 0.f;
        for (int s = 0; s < nspr; s++)
            tot += g_part[r * nspr + s];

        int lab = labels[r];
        if (lab < 0) lab = 0;
        if (lab >= V) lab = V - 1;
        const float target = __ldg(preds + (size_t)r * V + lab);

        double sum_others = (double)tot - (double)ex2(target * C);

        const double EPS = 1e-12;
        const double PI  = 3.14159265358979323846;
        double t = (double)target;
        t = fmin(fmax(t, -1.0 + EPS), 1.0 - EPS);
        double theta = acos(t);
        theta = fmin(fmax(theta, EPS), PI - EPS);
        double numerator = 30.0 * (cos(theta + 0.5) - 0.35);
        double denominator = exp(numerator) + sum_others;
        acc += numerator - log(denominator);
    }

    #pragma unroll
    for (int o = 16; o > 0; o >>= 1)
        acc += __shfl_xor_sync(0xffffffffu, acc, o);

    __shared__ double dwarp[8];
    const int wid = tid >> 5, lid = tid & 31;
    if (lid == 0) dwarp[wid] = acc;
    __syncthreads();

    if (tid == 0) {
        double tot = 0.0;
        #pragma unroll
        for (int w = 0; w < 8; w++) tot += dwarp[w];
        out[0] = (float)(-tot / (double)B);
    }
}

extern "C" void kernel_launch(void* const* d_in, const int* in_sizes, int n_in,
                              void* d_out, int out_size)
{
    const float* preds  = (const float*)d_in[0];
    const int*   labels = (const int*)d_in[1];

    const int B  = in_sizes[1];                 // 2048
    const int V  = in_sizes[0] / B;             // 32000
    const int n4 = V >> 2;                      // 8000 (V % 4 == 0 here)
    const int nspr = (n4 + SEG_F4 - 1) / SEG_F4;   // 8

    cosarc_sweep_kernel<<<B * nspr, 256>>>(preds, n4, nspr);
    cosarc_final_kernel<<<1, 256>>>(preds, labels, (float*)d_out, V, B, nspr);
}

// round 15
// speedup vs baseline: 2.1650x; 2.1650x over previous
#include <cuda_runtime.h>
#include <cuda_bf16.h>

#define MAX_PART 65536
#define SEG_F4   1000          // float4 per segment = 16 KB

__device__ float  g_part[MAX_PART];
__device__ double g_blk[64];
__device__ unsigned int g_done = 0;   // self-resets -> graph-replay safe

__device__ __forceinline__ float ex2(float x) {
    float y;
    asm("ex2.approx.f32 %0, %1;" : "=f"(y) : "f"(x));
    return y;
}

// Segment sweep: one 16KB CONTIGUOUS segment per block -> resident blocks
// cover a dense ~19MB sweeping window. R14 measured this at ~7.2 TB/s (the
// row-per-block designs' ~5 TB/s cap was DRAM footprint, not warp MLP).
__global__ void __launch_bounds__(256) cosarc_sweep_kernel(
    const float* __restrict__ preds,
    int n4, int nspr)               // n4 = V/4, nspr = segments per row
{
    const int b   = blockIdx.x;
    const int row = b / nspr;
    const int seg = b - row * nspr;
    const int base = seg * SEG_F4;

    const float4* p4 = reinterpret_cast<const float4*>(preds) + (size_t)row * n4 + base;
    const int lim = min(SEG_F4, n4 - base);   // 1000 except a short last segment

    const int tid = threadIdx.x;
    const float C = 30.0f * 1.4426950408889634f;   // exp(30x) = exp2(C*x)
    float s0 = 0.f, s1 = 0.f, s2 = 0.f, s3 = 0.f;

    // 4 front-batched independent LDG.128 (covers 1024 >= SEG_F4).
    const int i0 = tid, i1 = tid + 256, i2 = tid + 512, i3 = tid + 768;
    float4 a, bb, c, d;
    bool v0 = i0 < lim, v1 = i1 < lim, v2 = i2 < lim, v3 = i3 < lim;
    if (v0) a  = __ldg(p4 + i0);
    if (v1) bb = __ldg(p4 + i1);
    if (v2) c  = __ldg(p4 + i2);
    if (v3) d  = __ldg(p4 + i3);
    if (v0) { s0 += ex2(a.x  * C) + ex2(a.y  * C); s1 += ex2(a.z  * C) + ex2(a.w  * C); }
    if (v1) { s2 += ex2(bb.x * C) + ex2(bb.y * C); s3 += ex2(bb.z * C) + ex2(bb.w * C); }
    if (v2) { s0 += ex2(c.x  * C) + ex2(c.y  * C); s1 += ex2(c.z  * C) + ex2(c.w  * C); }
    if (v3) { s2 += ex2(d.x  * C) + ex2(d.y  * C); s3 += ex2(d.z  * C) + ex2(d.w  * C); }

    float sum = (s0 + s1) + (s2 + s3);
    #pragma unroll
    for (int o = 16; o > 0; o >>= 1)
        sum += __shfl_xor_sync(0xffffffffu, sum, o);

    __shared__ float warpsum[8];
    const int wid = tid >> 5, lid = tid & 31;
    if (lid == 0) warpsum[wid] = sum;
    __syncthreads();

    if (tid == 0) {
        float tot = 0.f;
        #pragma unroll
        for (int w = 0; w < 8; w++) tot += warpsum[w];
        g_part[b] = tot;
    }
}

// Epilogue: ONE THREAD PER ROW across 8 blocks (R14 lesson: 2048 serialized
// fp64 transcendental chains on one SM cost 85us; distributed they cost ~4us).
// Last-block-done sums the 8 block partials in fixed order -> deterministic.
__global__ void __launch_bounds__(256) cosarc_final_kernel(
    const float* __restrict__ preds,
    const int* __restrict__ labels,     // int32 (JAX x64 disabled)
    float* __restrict__ out,
    int V, int B, int nspr)
{
    const int tid = threadIdx.x;
    const int r = blockIdx.x * 256 + tid;
    const float C = 30.0f * 1.4426950408889634f;

    double loss = 0.0;
    if (r < B) {
        float tot = 0.f;
        #pragma unroll 8
        for (int s = 0; s < nspr; s++)
            tot += g_part[r * nspr + s];

        int lab = labels[r];
        if (lab < 0) lab = 0;
        if (lab >= V) lab = V - 1;
        const float target = __ldg(preds + (size_t)r * V + lab);

        double sum_others = (double)tot - (double)ex2(target * C);

        const double EPS = 1e-12;
        const double PI  = 3.14159265358979323846;
        double t = (double)target;
        t = fmin(fmax(t, -1.0 + EPS), 1.0 - EPS);
        double theta = acos(t);
        theta = fmin(fmax(theta, EPS), PI - EPS);
        double numerator = 30.0 * (cos(theta + 0.5) - 0.35);
        double denominator = exp(numerator) + sum_others;
        loss = numerator - log(denominator);
    }

    // Block reduce (doubles)
    #pragma unroll
    for (int o = 16; o > 0; o >>= 1)
        loss += __shfl_xor_sync(0xffffffffu, loss, o);

    __shared__ double dwarp[8];
    const int wid = tid >> 5, lid = tid & 31;
    if (lid == 0) dwarp[wid] = loss;
    __syncthreads();

    if (tid == 0) {
        double tot = 0.0;
        #pragma unroll
        for (int w = 0; w < 8; w++) tot += dwarp[w];
        g_blk[blockIdx.x] = tot;
    }

    // Last-block-done: fixed-order sum of block partials.
    __threadfence();
    __shared__ bool is_last;
    if (tid == 0)
        is_last = (atomicAdd(&g_done, 1u) == gridDim.x - 1);
    __syncthreads();

    if (is_last && tid == 0) {
        double tot = 0.0;
        for (unsigned int w = 0; w < gridDim.x; w++)
            tot += g_blk[w];
        out[0] = (float)(-tot / (double)B);
        g_done = 0;   // reset for next graph replay
    }
}

extern "C" void kernel_launch(void* const* d_in, const int* in_sizes, int n_in,
                              void* d_out, int out_size)
{
    const float* preds  = (const float*)d_in[0];
    const int*   labels = (const int*)d_in[1];

    const int B  = in_sizes[1];                 // 2048
    const int V  = in_sizes[0] / B;             // 32000
    const int n4 = V >> 2;                      // 8000 (V % 4 == 0 here)
    const int nspr = (n4 + SEG_F4 - 1) / SEG_F4;   // 8

    cosarc_sweep_kernel<<<B * nspr, 256>>>(preds, n4, nspr);
    cosarc_final_kernel<<<(B + 255) / 256, 256>>>(preds, labels, (float*)d_out, V, B, nspr);
}

// round 16
// speedup vs baseline: 2.5477x; 1.1767x over previous
#include <cuda_runtime.h>
#include <cuda_bf16.h>

#define MAX_PART 65536
#define SEG_F4   1000          // float4 per segment = 16 KB

__device__ float  g_part[MAX_PART];
__device__ double g_blk[64];
__device__ unsigned int g_done = 0;   // self-resets -> graph-replay safe

__device__ __forceinline__ float ex2(float x) {
    float y;
    asm("ex2.approx.f32 %0, %1;" : "=f"(y) : "f"(x));
    return y;
}
__device__ __forceinline__ float lg2(float x) {
    float y;
    asm("lg2.approx.f32 %0, %1;" : "=f"(y) : "f"(x));
    return y;
}

// Segment sweep: one 16KB CONTIGUOUS segment per block -> resident blocks
// cover a dense ~19MB sweeping window. Measured ~6.9-7.2 TB/s (R14/R15); the
// row-per-block designs' ~5 TB/s cap was DRAM footprint, not warp MLP.
__global__ void __launch_bounds__(256) cosarc_sweep_kernel(
    const float* __restrict__ preds,
    int n4, int nspr)               // n4 = V/4, nspr = segments per row
{
    const int b   = blockIdx.x;
    const int row = b / nspr;
    const int seg = b - row * nspr;
    const int base = seg * SEG_F4;

    const float4* p4 = reinterpret_cast<const float4*>(preds) + (size_t)row * n4 + base;
    const int lim = min(SEG_F4, n4 - base);   // 1000 except a short last segment

    const int tid = threadIdx.x;
    const float C = 30.0f * 1.4426950408889634f;   // exp(30x) = exp2(C*x)
    float s0 = 0.f, s1 = 0.f, s2 = 0.f, s3 = 0.f;

    // 4 front-batched independent LDG.128 (covers 1024 >= SEG_F4).
    const int i0 = tid, i1 = tid + 256, i2 = tid + 512, i3 = tid + 768;
    float4 a, bb, c, d;
    bool v0 = i0 < lim, v1 = i1 < lim, v2 = i2 < lim, v3 = i3 < lim;
    if (v0) a  = __ldg(p4 + i0);
    if (v1) bb = __ldg(p4 + i1);
    if (v2) c  = __ldg(p4 + i2);
    if (v3) d  = __ldg(p4 + i3);
    if (v0) { s0 += ex2(a.x  * C) + ex2(a.y  * C); s1 += ex2(a.z  * C) + ex2(a.w  * C); }
    if (v1) { s2 += ex2(bb.x * C) + ex2(bb.y * C); s3 += ex2(bb.z * C) + ex2(bb.w * C); }
    if (v2) { s0 += ex2(c.x  * C) + ex2(c.y  * C); s1 += ex2(c.z  * C) + ex2(c.w  * C); }
    if (v3) { s2 += ex2(d.x  * C) + ex2(d.y  * C); s3 += ex2(d.z  * C) + ex2(d.w  * C); }

    float sum = (s0 + s1) + (s2 + s3);
    #pragma unroll
    for (int o = 16; o > 0; o >>= 1)
        sum += __shfl_xor_sync(0xffffffffu, sum, o);

    __shared__ float warpsum[8];
    const int wid = tid >> 5, lid = tid & 31;
    if (lid == 0) warpsum[wid] = sum;
    __syncthreads();

    if (tid == 0) {
        float tot = 0.f;
        #pragma unroll
        for (int w = 0; w < 8; w++) tot += warpsum[w];
        g_part[b] = tot;
    }
}

// Epilogue: one thread per row, FP32 transcendentals (R15 lesson: the fp64
// acos/cos/exp/log chain cost 17us; fp32 FMA+MUFU chain is ~100 instrs).
// Error budget ~1e-5 relative per row << 1e-3 gate. Cross-row mean kept in
// double. Last-block-done sums block partials in fixed order (deterministic).
__global__ void __launch_bounds__(256) cosarc_final_kernel(
    const float* __restrict__ preds,
    const int* __restrict__ labels,     // int32 (JAX x64 disabled)
    float* __restrict__ out,
    int V, int B, int nspr)
{
    const int tid = threadIdx.x;
    const int r = blockIdx.x * 256 + tid;
    const float C = 30.0f * 1.4426950408889634f;
    const float LOG2E = 1.4426950408889634f;
    const float LN2   = 0.6931471805599453f;

    double loss = 0.0;
    if (r < B) {
        float tot = 0.f;
        #pragma unroll 8
        for (int s = 0; s < nspr; s++)
            tot += g_part[r * nspr + s];

        int lab = labels[r];
        if (lab < 0) lab = 0;
        if (lab >= V) lab = V - 1;
        const float target = __ldg(preds + (size_t)r * V + lab);

        float sum_others = tot - ex2(target * C);

        const float PI = 3.14159265358979323846f;
        float t = fminf(fmaxf(target, -1.0f + 1e-12f), 1.0f - 1e-7f);
        float theta = acosf(t);
        theta = fminf(fmaxf(theta, 1e-12f), PI - 1e-7f);
        float numerator = 30.0f * (__cosf(theta + 0.5f) - 0.35f);
        float denominator = ex2(numerator * LOG2E) + sum_others;
        loss = (double)(numerator - lg2(denominator) * LN2);
    }

    // Block reduce (doubles)
    #pragma unroll
    for (int o = 16; o > 0; o >>= 1)
        loss += __shfl_xor_sync(0xffffffffu, loss, o);

    __shared__ double dwarp[8];
    const int wid = tid >> 5, lid = tid & 31;
    if (lid == 0) dwarp[wid] = loss;
    __syncthreads();

    if (tid == 0) {
        double tot = 0.0;
        #pragma unroll
        for (int w = 0; w < 8; w++) tot += dwarp[w];
        g_blk[blockIdx.x] = tot;
    }

    // Last-block-done: fixed-order sum of block partials.
    __threadfence();
    __shared__ bool is_last;
    if (tid == 0)
        is_last = (atomicAdd(&g_done, 1u) == gridDim.x - 1);
    __syncthreads();

    if (is_last && tid == 0) {
        double tot = 0.0;
        for (unsigned int w = 0; w < gridDim.x; w++)
            tot += g_blk[w];
        out[0] = (float)(-tot / (double)B);
        g_done = 0;   // reset for next graph replay
    }
}

extern "C" void kernel_launch(void* const* d_in, const int* in_sizes, int n_in,
                              void* d_out, int out_size)
{
    const float* preds  = (const float*)d_in[0];
    const int*   labels = (const int*)d_in[1];

    const int B  = in_sizes[1];                 // 2048
    const int V  = in_sizes[0] / B;             // 32000
    const int n4 = V >> 2;                      // 8000 (V % 4 == 0 here)
    const int nspr = (n4 + SEG_F4 - 1) / SEG_F4;   // 8

    cosarc_sweep_kernel<<<B * nspr, 256>>>(preds, n4, nspr);
    cosarc_final_kernel<<<(B + 255) / 256, 256>>>(preds, labels, (float*)d_out, V, B, nspr);
}